// round 5
// baseline (speedup 1.0000x reference)
#include <cuda_runtime.h>
#include <cstdint>

// Fixed shapes: B=8, H=W=512
#define BB 8
#define NN (512*512)          // 262144 pixels per row
#define PP (BB*NN)
#define THREADS 256
#define TILE 2048             // px per block, k_compute
#define BLKX (NN/TILE)        // 128
#define STILE 4096            // px per block, k_cand
#define SBLKX (NN/STILE)      // 64
#define NB1 8192              // 13-bit digit1 bins
#define SH1 19                // digit1 = key >> 19
#define NB2 2048              // 11-bit digit2 bins
#define SH2 8                 // digit2 = (key >> 8) & 2047
#define EQCAP 32768
#define TIECAP 1024

// ---------------- device scratch ----------------
__device__ uint32_t g_keys[PP];       // 8 MB
__device__ uint32_t g_pl3[PP];        // 8 MB  loss3, target in sign bit
__device__ uint32_t g_hist[BB*NB1];
__device__ uint32_t g_sel1[BB];
__device__ int      g_kneed[BB];      // remaining count within selected bin
__device__ int      g_eqcount[BB];
__device__ uint32_t g_eqkey[BB*EQCAP];
__device__ uint32_t g_eqidx[BB*EQCAP];
__device__ int      g_done1[BB];
__device__ int      g_done2[BB];
__device__ int      g_rows_done;
__device__ double   g_sum_l3;
__device__ unsigned long long g_sum_tsel;
__device__ unsigned long long g_ttotal;

__device__ __forceinline__ uint32_t f2mono(float f) {
    uint32_t u = __float_as_uint(f);
    return (u & 0x80000000u) ? ~u : (u | 0x80000000u);
}

// Robust scalar read (f32 vs f64 sniff; true values are in (0,1)).
__device__ __forceinline__ double read_scalar(const void* p) {
    float f = *(const float*)p;
    if (f > 1e-6f && f < 1.0f) return (double)f;
    return *(const double*)p;
}

// 2-class log-softmax: 3 MUFU ops.
__device__ __forceinline__ void sm2(float x0, float x1,
                                    float& lp0, float& lp1, float& p0, float& p1) {
    float d = x0 - x1;
    float t = __expf(fminf(-d, 80.0f));
    p0 = __fdividef(1.0f, 1.0f + t);
    p1 = t * p0;
    lp0 = __logf(p0);
    lp1 = lp0 - d;
}

__device__ __forceinline__ void pixel_loss(float a1, float c1, float a2, float c2,
                                           float a3, float c3, int t,
                                           float kdw, float w,
                                           float& loss, float& l3) {
    float lp10, lp11, p10, p11; sm2(a1, c1, lp10, lp11, p10, p11);
    float lp20, lp21, p20, p21; sm2(a2, c2, lp20, lp21, p20, p21);
    float lp30, lp31, p30, p31; sm2(a3, c3, lp30, lp31, p30, p31);
    float tf = (float)t;
    float om11 = 1.0f - p11, om10 = 1.0f - p10;
    float om21 = 1.0f - p21, om20 = 1.0f - p20;
    float om31 = 1.0f - p31, om30 = 1.0f - p30;
    float l1 = -tf * om11*om11*lp11 - (1.0f-tf) * om10*om10*lp10;
    float l2 = -tf * om21*om21*lp21 - (1.0f-tf) * om20*om20*lp20;
    l3       = -tf * om31*om31*lp31 - (1.0f-tf) * om30*om30*lp30;
    float kdl12 = p10*(lp10-lp20) + p11*(lp11-lp21);
    float kdl21 = p20*(lp20-lp10) + p21*(lp21-lp11);
    loss = w * (l1 + l2 + l3) + kdw * (kdl12 + kdl21);
}

// ---------------- kernels ----------------

__global__ void k_init() {
    int tid = threadIdx.x + blockIdx.x * blockDim.x;
    int stride = gridDim.x * blockDim.x;
    for (int i = tid; i < BB*NB1; i += stride) g_hist[i] = 0u;
    if (blockIdx.x == 0) {
        if (threadIdx.x < BB) {
            g_eqcount[threadIdx.x] = 0;
            g_done1[threadIdx.x]   = 0;
            g_done2[threadIdx.x]   = 0;
        }
        if (threadIdx.x == 0) {
            g_sum_l3 = 0.0; g_sum_tsel = 0ull; g_ttotal = 0ull; g_rows_done = 0;
        }
    }
}

// Fused math + key/payload store + 8192-bin hist + target total
// + per-row last-block select of digit1.
__global__ void __launch_bounds__(THREADS)
k_compute(const float* __restrict__ in1, const float* __restrict__ in2,
          const float* __restrict__ in3, const int* __restrict__ tgt,
          const void* __restrict__ kdw_p, const void* __restrict__ forget_p)
{
    __shared__ uint32_t sh[NB1];
    __shared__ unsigned ss[256];
    __shared__ int swt[8];
    __shared__ int s_last;
    int tid = threadIdx.x;
#pragma unroll
    for (int i = 0; i < NB1/THREADS; i++) sh[tid + i*THREADS] = 0u;
    __syncthreads();

    const int row = blockIdx.y;
    const float kdw = (float)read_scalar(kdw_p);
    const float w   = 1.0f - kdw;

    const float4* b1a = (const float4*)(in1 + (size_t)row * 2 * NN);
    const float4* b1c = (const float4*)(in1 + (size_t)row * 2 * NN + NN);
    const float4* b2a = (const float4*)(in2 + (size_t)row * 2 * NN);
    const float4* b2c = (const float4*)(in2 + (size_t)row * 2 * NN + NN);
    const float4* b3a = (const float4*)(in3 + (size_t)row * 2 * NN);
    const float4* b3c = (const float4*)(in3 + (size_t)row * 2 * NN + NN);
    const int4*   bt  = (const int4*)(tgt + (size_t)row * NN);
    uint4* kout = (uint4*)(g_keys + (size_t)row * NN);
    uint4* pout = (uint4*)(g_pl3  + (size_t)row * NN);

    int tcnt = 0;

#pragma unroll
    for (int g = 0; g < 2; g++) {
        int vi = (blockIdx.x * TILE + g * (TILE/2)) / 4 + tid;
        float4 A1 = b1a[vi], C1 = b1c[vi];
        float4 A2 = b2a[vi], C2 = b2c[vi];
        float4 A3 = b3a[vi], C3 = b3c[vi];
        int4   T  = bt[vi];

        float ls0, ls1, ls2, ls3, l30, l31, l32, l33;
        pixel_loss(A1.x, C1.x, A2.x, C2.x, A3.x, C3.x, T.x, kdw, w, ls0, l30);
        pixel_loss(A1.y, C1.y, A2.y, C2.y, A3.y, C3.y, T.y, kdw, w, ls1, l31);
        pixel_loss(A1.z, C1.z, A2.z, C2.z, A3.z, C3.z, T.z, kdw, w, ls2, l32);
        pixel_loss(A1.w, C1.w, A2.w, C2.w, A3.w, C3.w, T.w, kdw, w, ls3, l33);

        uint4 K = make_uint4(f2mono(ls0), f2mono(ls1), f2mono(ls2), f2mono(ls3));
        kout[vi] = K;
        uint4 P = make_uint4(__float_as_uint(l30) | ((uint32_t)T.x << 31),
                             __float_as_uint(l31) | ((uint32_t)T.y << 31),
                             __float_as_uint(l32) | ((uint32_t)T.z << 31),
                             __float_as_uint(l33) | ((uint32_t)T.w << 31));
        pout[vi] = P;

        atomicAdd(&sh[K.x >> SH1], 1u);
        atomicAdd(&sh[K.y >> SH1], 1u);
        atomicAdd(&sh[K.z >> SH1], 1u);
        atomicAdd(&sh[K.w >> SH1], 1u);
        tcnt += T.x + T.y + T.z + T.w;
    }
    __syncthreads();
#pragma unroll
    for (int i = 0; i < NB1/THREADS; i++) {
        uint32_t v = sh[tid + i*THREADS];
        if (v) atomicAdd(&g_hist[row * NB1 + tid + i*THREADS], v);
    }

#pragma unroll
    for (int o = 16; o; o >>= 1) tcnt += __shfl_down_sync(0xffffffffu, tcnt, o);
    if ((tid & 31) == 0) swt[tid >> 5] = tcnt;
    __syncthreads();
    if (tid == 0) {
        int s = 0;
#pragma unroll
        for (int i = 0; i < 8; i++) s += swt[i];
        atomicAdd(&g_ttotal, (unsigned long long)s);
    }

    // ---- last-block-per-row: select digit1 ----
    __threadfence();
    if (tid == 0) s_last = (atomicAdd(&g_done1[row], 1) == BLKX - 1);
    __syncthreads();
    if (!s_last) return;

    double rem = 1.0 - read_scalar(forget_p);
    unsigned kneed = (unsigned)(rem * (double)NN);

    const uint32_t* h = g_hist + row * NB1;
    unsigned lsum = 0;
#pragma unroll
    for (int i = 0; i < NB1/THREADS; i++) lsum += __ldcg(&h[tid * (NB1/THREADS) + i]);
    ss[tid] = lsum;
    __syncthreads();
    for (int off = 1; off < 256; off <<= 1) {
        unsigned n = (tid >= off) ? ss[tid - off] : 0u;
        __syncthreads();
        ss[tid] += n;
        __syncthreads();
    }
    unsigned incl = ss[tid];
    unsigned excl = incl - lsum;
    if (excl < kneed && kneed <= incl) {
        unsigned cum = excl;
#pragma unroll
        for (int i = 0; i < NB1/THREADS; i++) {
            unsigned v = __ldcg(&h[tid * (NB1/THREADS) + i]);
            if (cum + v >= kneed) {
                g_sel1[row]  = (uint32_t)(tid * (NB1/THREADS) + i);
                g_kneed[row] = (int)(kneed - cum);
                break;
            }
            cum += v;
        }
    }
}

// Pass over keys+payload: sum strictly-below-bin, collect in-bin candidates.
// Last block per row resolves candidates in smem; last row writes outputs.
__global__ void __launch_bounds__(THREADS)
k_cand(const void* __restrict__ forget_p, float* __restrict__ out)
{
    __shared__ uint32_t sh2[NB2];
    __shared__ unsigned ss[256];
    __shared__ double sd[8];
    __shared__ int    si[8];
    __shared__ uint32_t tkey[TIECAP];
    __shared__ uint32_t tidx[TIECAP];
    __shared__ int s_flag, s_tc, s_sel2, s_kneed2;

    int tid = threadIdx.x;
    int row = blockIdx.y;
    uint32_t sel1 = g_sel1[row];
    const uint4* keys = (const uint4*)(g_keys + (size_t)row * NN);
    const uint4* pl3  = (const uint4*)(g_pl3  + (size_t)row * NN);

    double sld = 0.0;
    int    st = 0;

#pragma unroll
    for (int it = 0; it < STILE/(THREADS*4); it++) {
        int vi = blockIdx.x * (STILE/4) + it * THREADS + tid;
        uint4 K = keys[vi];
        uint4 P = pl3[vi];
        uint32_t ks[4] = {K.x, K.y, K.z, K.w};
        uint32_t ps[4] = {P.x, P.y, P.z, P.w};
        float sl = 0.0f;
#pragma unroll
        for (int j = 0; j < 4; j++) {
            uint32_t d1 = ks[j] >> SH1;
            if (d1 < sel1) {
                sl += __uint_as_float(ps[j] & 0x7fffffffu);
                st += (int)(ps[j] >> 31);
            } else if (d1 == sel1) {
                int p = atomicAdd(&g_eqcount[row], 1);
                if (p < EQCAP) {
                    g_eqkey[row * EQCAP + p] = ks[j];
                    g_eqidx[row * EQCAP + p] = (uint32_t)(vi * 4 + j);
                }
            }
        }
        sld += (double)sl;
    }
#pragma unroll
    for (int o = 16; o; o >>= 1) {
        sld += __shfl_down_sync(0xffffffffu, sld, o);
        st  += __shfl_down_sync(0xffffffffu, st, o);
    }
    if ((tid & 31) == 0) { sd[tid >> 5] = sld; si[tid >> 5] = st; }
    __syncthreads();
    if (tid == 0) {
        double S = 0.0; int Ti = 0;
#pragma unroll
        for (int i = 0; i < 8; i++) { S += sd[i]; Ti += si[i]; }
        atomicAdd(&g_sum_l3, S);
        atomicAdd(&g_sum_tsel, (unsigned long long)Ti);
    }

    // ---- last block per row: resolve candidates ----
    __threadfence();
    if (tid == 0) s_flag = (atomicAdd(&g_done2[row], 1) == SBLKX - 1);
    __syncthreads();
    if (!s_flag) return;

    int c = atomicAdd(&g_eqcount[row], 0);
    if (c > EQCAP) c = EQCAP;
    int kneed1 = g_kneed[row];
    const uint32_t* ek = g_eqkey + row * EQCAP;
    const uint32_t* ei = g_eqidx + row * EQCAP;

    // hist of digit2 over candidates
#pragma unroll
    for (int i = 0; i < NB2/THREADS; i++) sh2[tid + i*THREADS] = 0u;
    if (tid == 0) s_tc = 0;
    __syncthreads();
    for (int i = tid; i < c; i += THREADS)
        atomicAdd(&sh2[(__ldcg(&ek[i]) >> SH2) & (NB2-1)], 1u);
    __syncthreads();

    // select digit2
    unsigned lsum = 0;
#pragma unroll
    for (int i = 0; i < NB2/THREADS; i++) lsum += sh2[tid * (NB2/THREADS) + i];
    ss[tid] = lsum;
    __syncthreads();
    for (int off = 1; off < 256; off <<= 1) {
        unsigned n = (tid >= off) ? ss[tid - off] : 0u;
        __syncthreads();
        ss[tid] += n;
        __syncthreads();
    }
    unsigned incl = ss[tid];
    unsigned excl = incl - lsum;
    if (excl < (unsigned)kneed1 && (unsigned)kneed1 <= incl) {
        unsigned cum = excl;
#pragma unroll
        for (int i = 0; i < NB2/THREADS; i++) {
            unsigned v = sh2[tid * (NB2/THREADS) + i];
            if (cum + v >= (unsigned)kneed1) {
                s_sel2   = tid * (NB2/THREADS) + i;
                s_kneed2 = (int)((unsigned)kneed1 - cum);
                break;
            }
            cum += v;
        }
    }
    __syncthreads();
    int sel2 = s_sel2, kneed2 = s_kneed2;

    // sum candidates below digit2, collect exact ties
    double sl2 = 0.0;
    int    st2 = 0;
    for (int i = tid; i < c; i += THREADS) {
        uint32_t k = __ldcg(&ek[i]);
        int d = (int)((k >> SH2) & (NB2-1));
        if (d < sel2) {
            uint32_t idx = __ldcg(&ei[i]);
            uint32_t p = __ldcg(&g_pl3[(size_t)row * NN + idx]);
            sl2 += (double)__uint_as_float(p & 0x7fffffffu);
            st2 += (int)(p >> 31);
        } else if (d == sel2) {
            int tp = atomicAdd(&s_tc, 1);
            if (tp < TIECAP) { tkey[tp] = k; tidx[tp] = __ldcg(&ei[i]); }
        }
    }
    __syncthreads();
    int tc = min(s_tc, TIECAP);

    // exact rank-select among ties by (key, idx) — stable-argsort equivalent
    for (int j = tid; j < tc; j += THREADS) {
        uint32_t kj = tkey[j], ij = tidx[j];
        int rank = 0;
        for (int q = 0; q < tc; q++) {
            uint32_t kq = tkey[q], iq = tidx[q];
            rank += (kq < kj || (kq == kj && iq < ij)) ? 1 : 0;
        }
        if (rank < kneed2) {
            uint32_t p = __ldcg(&g_pl3[(size_t)row * NN + ij]);
            sl2 += (double)__uint_as_float(p & 0x7fffffffu);
            st2 += (int)(p >> 31);
        }
    }
#pragma unroll
    for (int o = 16; o; o >>= 1) {
        sl2 += __shfl_down_sync(0xffffffffu, sl2, o);
        st2 += __shfl_down_sync(0xffffffffu, st2, o);
    }
    if ((tid & 31) == 0) { sd[tid >> 5] = sl2; si[tid >> 5] = st2; }
    __syncthreads();
    if (tid == 0) {
        double S = 0.0; int Ti = 0;
#pragma unroll
        for (int i = 0; i < 8; i++) { S += sd[i]; Ti += si[i]; }
        atomicAdd(&g_sum_l3, S);
        atomicAdd(&g_sum_tsel, (unsigned long long)Ti);

        // ---- globally last row writes the outputs ----
        __threadfence();
        if (atomicAdd(&g_rows_done, 1) == BB - 1) {
            double sl = atomicAdd(&g_sum_l3, 0.0);
            unsigned long long ts = atomicAdd(&g_sum_tsel, 0ull);
            unsigned long long tt = atomicAdd(&g_ttotal, 0ull);
            double rem = 1.0 - read_scalar(forget_p);
            long long num_rem = (long long)(rem * (double)NN);
            double denom = (double)BB * (double)num_rem;
            out[0] = (float)(sl / denom);
            out[1] = (float)((double)ts / (double)tt);
        }
    }
}

// ---------------- host entry ----------------
extern "C" void kernel_launch(void* const* d_in, const int* in_sizes, int n_in,
                              void* d_out, int out_size) {
    const float* in1    = (const float*)d_in[0];
    const float* in2    = (const float*)d_in[1];
    const float* in3    = (const float*)d_in[2];
    const int*   tgt    = (const int*)d_in[3];
    const void*  forget = d_in[4];
    const void*  kdw    = d_in[5];
    float* out = (float*)d_out;

    k_init<<<32, 256>>>();
    k_compute<<<dim3(BLKX, BB), THREADS>>>(in1, in2, in3, tgt, kdw, forget);
    k_cand<<<dim3(SBLKX, BB), THREADS>>>(forget, out);

    (void)in_sizes; (void)n_in; (void)out_size;
}

// round 6
// speedup vs baseline: 2.9515x; 2.9515x over previous
#include <cuda_runtime.h>
#include <cstdint>

// Fixed shapes: B=8, H=W=512
#define BB 8
#define NN (512*512)          // 262144 pixels per row
#define PP (BB*NN)
#define THREADS 256
#define TILE 2048             // px per block, k_compute
#define BLKX (NN/TILE)        // 128
#define STILE 4096            // px per block, k_hist / k_sum
#define SBLKX (NN/STILE)      // 64
#define NB 2048               // 11-bit digit bins
#define SH1 21                // digit1 = key >> 21           (11 bits)
#define SH2 10                // digit2 = (key >> 10) & 2047  (11 bits)
#define EQCAP 2048
#define TIECAP 2048

// ---------------- device scratch (zero-initialized at load; every kernel
// restores the all-zero invariant on the counters/hist/sums it consumes) ----
__device__ uint32_t g_keys[PP];       // 8 MB
__device__ uint32_t g_pl3[PP];        // 8 MB  loss3, target in sign bit
__device__ uint32_t g_hist[BB*NB];    // zero-invariant
__device__ uint32_t g_sel1[BB];
__device__ uint32_t g_thr[BB];
__device__ int      g_kneed[BB];
__device__ int      g_eqcount[BB];    // zero-invariant
__device__ uint32_t g_eqkey[BB*EQCAP];
__device__ uint32_t g_eqidx[BB*EQCAP];
__device__ int      g_done1[BB];      // zero-invariant tickets
__device__ int      g_done2[BB];
__device__ int      g_done3[BB];
__device__ int      g_rows_done;
__device__ double   g_sum_l3;         // zero-invariant
__device__ unsigned long long g_sum_tsel;
__device__ unsigned long long g_ttotal;

__device__ __forceinline__ uint32_t f2mono(float f) {
    uint32_t u = __float_as_uint(f);
    return (u & 0x80000000u) ? ~u : (u | 0x80000000u);
}

// Robust scalar read (f32 vs f64 sniff; true values are in (0,1)).
__device__ __forceinline__ double read_scalar(const void* p) {
    float f = *(const float*)p;
    if (f > 1e-6f && f < 1.0f) return (double)f;
    return *(const double*)p;
}

// 2-class log-softmax: 3 MUFU ops.
__device__ __forceinline__ void sm2(float x0, float x1,
                                    float& lp0, float& lp1, float& p0, float& p1) {
    float d = x0 - x1;
    float t = __expf(fminf(-d, 80.0f));
    p0 = __fdividef(1.0f, 1.0f + t);
    p1 = t * p0;
    lp0 = __logf(p0);
    lp1 = lp0 - d;
}

__device__ __forceinline__ void pixel_loss(float a1, float c1, float a2, float c2,
                                           float a3, float c3, int t,
                                           float kdw, float w,
                                           float& loss, float& l3) {
    float lp10, lp11, p10, p11; sm2(a1, c1, lp10, lp11, p10, p11);
    float lp20, lp21, p20, p21; sm2(a2, c2, lp20, lp21, p20, p21);
    float lp30, lp31, p30, p31; sm2(a3, c3, lp30, lp31, p30, p31);
    float tf = (float)t;
    float om11 = 1.0f - p11, om10 = 1.0f - p10;
    float om21 = 1.0f - p21, om20 = 1.0f - p20;
    float om31 = 1.0f - p31, om30 = 1.0f - p30;
    float l1 = -tf * om11*om11*lp11 - (1.0f-tf) * om10*om10*lp10;
    float l2 = -tf * om21*om21*lp21 - (1.0f-tf) * om20*om20*lp20;
    l3       = -tf * om31*om31*lp31 - (1.0f-tf) * om30*om30*lp30;
    float kdl12 = p10*(lp10-lp20) + p11*(lp11-lp21);
    float kdl21 = p20*(lp20-lp10) + p21*(lp21-lp11);
    loss = w * (l1 + l2 + l3) + kdw * (kdl12 + kdl21);
}

// ---------------- kernel 1: math + digit1 hist + fused select ----------------
__global__ void __launch_bounds__(THREADS)
k_compute(const float* __restrict__ in1, const float* __restrict__ in2,
          const float* __restrict__ in3, const int* __restrict__ tgt,
          const void* __restrict__ kdw_p, const void* __restrict__ forget_p)
{
    __shared__ uint32_t sh[NB];
    __shared__ unsigned ss[256];
    __shared__ int swt[8];
    __shared__ int s_last;
    int tid = threadIdx.x;
#pragma unroll
    for (int i = 0; i < NB/THREADS; i++) sh[tid + i*THREADS] = 0u;
    __syncthreads();

    const int row = blockIdx.y;
    const float kdw = (float)read_scalar(kdw_p);
    const float w   = 1.0f - kdw;

    const float4* b1a = (const float4*)(in1 + (size_t)row * 2 * NN);
    const float4* b1c = (const float4*)(in1 + (size_t)row * 2 * NN + NN);
    const float4* b2a = (const float4*)(in2 + (size_t)row * 2 * NN);
    const float4* b2c = (const float4*)(in2 + (size_t)row * 2 * NN + NN);
    const float4* b3a = (const float4*)(in3 + (size_t)row * 2 * NN);
    const float4* b3c = (const float4*)(in3 + (size_t)row * 2 * NN + NN);
    const int4*   bt  = (const int4*)(tgt + (size_t)row * NN);
    uint4* kout = (uint4*)(g_keys + (size_t)row * NN);
    uint4* pout = (uint4*)(g_pl3  + (size_t)row * NN);

    int tcnt = 0;

#pragma unroll
    for (int g = 0; g < 2; g++) {
        int vi = (blockIdx.x * TILE + g * (TILE/2)) / 4 + tid;
        float4 A1 = b1a[vi], C1 = b1c[vi];
        float4 A2 = b2a[vi], C2 = b2c[vi];
        float4 A3 = b3a[vi], C3 = b3c[vi];
        int4   T  = bt[vi];

        float ls0, ls1, ls2, ls3, l30, l31, l32, l33;
        pixel_loss(A1.x, C1.x, A2.x, C2.x, A3.x, C3.x, T.x, kdw, w, ls0, l30);
        pixel_loss(A1.y, C1.y, A2.y, C2.y, A3.y, C3.y, T.y, kdw, w, ls1, l31);
        pixel_loss(A1.z, C1.z, A2.z, C2.z, A3.z, C3.z, T.z, kdw, w, ls2, l32);
        pixel_loss(A1.w, C1.w, A2.w, C2.w, A3.w, C3.w, T.w, kdw, w, ls3, l33);

        uint4 K = make_uint4(f2mono(ls0), f2mono(ls1), f2mono(ls2), f2mono(ls3));
        kout[vi] = K;
        uint4 P = make_uint4(__float_as_uint(l30) | ((uint32_t)T.x << 31),
                             __float_as_uint(l31) | ((uint32_t)T.y << 31),
                             __float_as_uint(l32) | ((uint32_t)T.z << 31),
                             __float_as_uint(l33) | ((uint32_t)T.w << 31));
        pout[vi] = P;

        atomicAdd(&sh[K.x >> SH1], 1u);
        atomicAdd(&sh[K.y >> SH1], 1u);
        atomicAdd(&sh[K.z >> SH1], 1u);
        atomicAdd(&sh[K.w >> SH1], 1u);
        tcnt += T.x + T.y + T.z + T.w;
    }
    __syncthreads();
#pragma unroll
    for (int i = 0; i < NB/THREADS; i++) {
        uint32_t v = sh[tid + i*THREADS];
        if (v) atomicAdd(&g_hist[row * NB + tid + i*THREADS], v);
    }

#pragma unroll
    for (int o = 16; o; o >>= 1) tcnt += __shfl_down_sync(0xffffffffu, tcnt, o);
    if ((tid & 31) == 0) swt[tid >> 5] = tcnt;
    __syncthreads();
    if (tid == 0) {
        int s = 0;
#pragma unroll
        for (int i = 0; i < 8; i++) s += swt[i];
        atomicAdd(&g_ttotal, (unsigned long long)s);
    }

    // ---- last block of this row: select digit1, zero hist, reset ticket ----
    __threadfence();
    if (tid == 0) s_last = (atomicAdd(&g_done1[row], 1) == BLKX - 1);
    __syncthreads();
    if (!s_last) return;
    if (tid == 0) g_done1[row] = 0;

    double rem = 1.0 - read_scalar(forget_p);
    unsigned kneed = (unsigned)(rem * (double)NN);

    uint32_t* h = g_hist + row * NB;
    unsigned local[NB/THREADS];
    unsigned lsum = 0;
#pragma unroll
    for (int i = 0; i < NB/THREADS; i++) {
        local[i] = __ldcg(&h[tid * (NB/THREADS) + i]);
        lsum += local[i];
        h[tid * (NB/THREADS) + i] = 0u;       // restore zero-invariant
    }
    ss[tid] = lsum;
    __syncthreads();
    for (int off = 1; off < 256; off <<= 1) {
        unsigned n = (tid >= off) ? ss[tid - off] : 0u;
        __syncthreads();
        ss[tid] += n;
        __syncthreads();
    }
    unsigned incl = ss[tid];
    unsigned excl = incl - lsum;
    if (excl < kneed && kneed <= incl) {
        unsigned cum = excl;
#pragma unroll
        for (int i = 0; i < NB/THREADS; i++) {
            if (cum + local[i] >= kneed) {
                g_sel1[row]  = (uint32_t)(tid * (NB/THREADS) + i);
                g_kneed[row] = (int)(kneed - cum);
                break;
            }
            cum += local[i];
        }
    }
}

// ---------------- kernel 2: digit2 hist (direct global atomics) + select ----
__global__ void __launch_bounds__(THREADS)
k_hist()
{
    __shared__ unsigned ss[256];
    __shared__ int s_last;
    int tid = threadIdx.x;
    int row = blockIdx.y;
    uint32_t sel1 = g_sel1[row];
    const uint4* keys = (const uint4*)(g_keys + (size_t)row * NN);

#pragma unroll
    for (int it = 0; it < STILE/(THREADS*4); it++) {
        int vi = blockIdx.x * (STILE/4) + it * THREADS + tid;
        uint4 K = keys[vi];
        uint32_t ks[4] = {K.x, K.y, K.z, K.w};
#pragma unroll
        for (int j = 0; j < 4; j++)
            if ((ks[j] >> SH1) == sel1)
                atomicAdd(&g_hist[row * NB + ((ks[j] >> SH2) & (NB-1))], 1u);
    }

    // ---- last block of this row: select digit2, zero hist, reset ticket ----
    __threadfence();
    if (tid == 0) s_last = (atomicAdd(&g_done2[row], 1) == SBLKX - 1);
    __syncthreads();
    if (!s_last) return;
    if (tid == 0) g_done2[row] = 0;

    unsigned kneed1 = (unsigned)g_kneed[row];
    uint32_t* h = g_hist + row * NB;
    unsigned local[NB/THREADS];
    unsigned lsum = 0;
#pragma unroll
    for (int i = 0; i < NB/THREADS; i++) {
        local[i] = __ldcg(&h[tid * (NB/THREADS) + i]);
        lsum += local[i];
        h[tid * (NB/THREADS) + i] = 0u;       // restore zero-invariant
    }
    ss[tid] = lsum;
    __syncthreads();
    for (int off = 1; off < 256; off <<= 1) {
        unsigned n = (tid >= off) ? ss[tid - off] : 0u;
        __syncthreads();
        ss[tid] += n;
        __syncthreads();
    }
    unsigned incl = ss[tid];
    unsigned excl = incl - lsum;
    if (excl < kneed1 && kneed1 <= incl) {
        unsigned cum = excl;
#pragma unroll
        for (int i = 0; i < NB/THREADS; i++) {
            if (cum + local[i] >= kneed1) {
                uint32_t sel2 = (uint32_t)(tid * (NB/THREADS) + i);
                g_thr[row]   = ((sel1 << 11) | sel2) << SH2;
                g_kneed[row] = (int)(kneed1 - cum);
                break;
            }
            cum += local[i];
        }
    }
}

// ---------------- kernel 3: threshold sum + tie resolve + output ------------
__global__ void __launch_bounds__(THREADS)
k_sum(const void* __restrict__ forget_p, float* __restrict__ out)
{
    __shared__ double sd[8];
    __shared__ int    si[8];
    __shared__ uint32_t tkey[TIECAP];
    __shared__ uint32_t tidx[TIECAP];
    __shared__ int s_last;

    int tid = threadIdx.x;
    int row = blockIdx.y;
    uint32_t thr = g_thr[row];
    uint32_t pfx22 = thr >> SH2;
    const uint4* keys = (const uint4*)(g_keys + (size_t)row * NN);
    const uint4* pl3  = (const uint4*)(g_pl3  + (size_t)row * NN);

    double sld = 0.0;
    int    st = 0;

#pragma unroll
    for (int it = 0; it < STILE/(THREADS*4); it++) {
        int vi = blockIdx.x * (STILE/4) + it * THREADS + tid;
        uint4 K = keys[vi];
        uint4 P = pl3[vi];
        uint32_t ks[4] = {K.x, K.y, K.z, K.w};
        uint32_t ps[4] = {P.x, P.y, P.z, P.w};
        float sl = 0.0f;
#pragma unroll
        for (int j = 0; j < 4; j++) {
            if (ks[j] < thr) {
                sl += __uint_as_float(ps[j] & 0x7fffffffu);
                st += (int)(ps[j] >> 31);
            } else if ((ks[j] >> SH2) == pfx22) {   // tie bin (~tens per row)
                int p = atomicAdd(&g_eqcount[row], 1);
                if (p < EQCAP) {
                    g_eqkey[row * EQCAP + p] = ks[j];
                    g_eqidx[row * EQCAP + p] = (uint32_t)(vi * 4 + j);
                }
            }
        }
        sld += (double)sl;
    }
#pragma unroll
    for (int o = 16; o; o >>= 1) {
        sld += __shfl_down_sync(0xffffffffu, sld, o);
        st  += __shfl_down_sync(0xffffffffu, st, o);
    }
    if ((tid & 31) == 0) { sd[tid >> 5] = sld; si[tid >> 5] = st; }
    __syncthreads();
    if (tid == 0) {
        double S = 0.0; int Ti = 0;
#pragma unroll
        for (int i = 0; i < 8; i++) { S += sd[i]; Ti += si[i]; }
        atomicAdd(&g_sum_l3, S);
        atomicAdd(&g_sum_tsel, (unsigned long long)Ti);
    }

    // ---- last block of this row: resolve ties, maybe write outputs ----
    __threadfence();
    if (tid == 0) s_last = (atomicAdd(&g_done3[row], 1) == SBLKX - 1);
    __syncthreads();
    if (!s_last) return;

    int c = min(__ldcg(&g_eqcount[row]), EQCAP);
    if (tid == 0) { g_done3[row] = 0; g_eqcount[row] = 0; }  // restore invariant
    int kneed2 = g_kneed[row];

    for (int i = tid; i < c; i += THREADS) {
        tkey[i] = __ldcg(&g_eqkey[row * EQCAP + i]);
        tidx[i] = __ldcg(&g_eqidx[row * EQCAP + i]);
    }
    __syncthreads();

    // exact rank-select by (key, idx) — equivalent to stable argsort order
    double sl2 = 0.0;
    int    st2 = 0;
    for (int j = tid; j < c; j += THREADS) {
        uint32_t kj = tkey[j], ij = tidx[j];
        int rank = 0;
        for (int q = 0; q < c; q++) {
            uint32_t kq = tkey[q], iq = tidx[q];
            rank += (kq < kj || (kq == kj && iq < ij)) ? 1 : 0;
        }
        if (rank < kneed2) {
            uint32_t p = __ldcg(&g_pl3[(size_t)row * NN + ij]);
            sl2 += (double)__uint_as_float(p & 0x7fffffffu);
            st2 += (int)(p >> 31);
        }
    }
#pragma unroll
    for (int o = 16; o; o >>= 1) {
        sl2 += __shfl_down_sync(0xffffffffu, sl2, o);
        st2 += __shfl_down_sync(0xffffffffu, st2, o);
    }
    if ((tid & 31) == 0) { sd[tid >> 5] = sl2; si[tid >> 5] = st2; }
    __syncthreads();
    if (tid != 0) return;

    double S = 0.0; int Ti = 0;
#pragma unroll
    for (int i = 0; i < 8; i++) { S += sd[i]; Ti += si[i]; }
    atomicAdd(&g_sum_l3, S);
    atomicAdd(&g_sum_tsel, (unsigned long long)Ti);

    __threadfence();
    if (atomicAdd(&g_rows_done, 1) == BB - 1) {
        double sl = atomicAdd(&g_sum_l3, 0.0);
        unsigned long long ts = atomicAdd(&g_sum_tsel, 0ull);
        unsigned long long tt = atomicAdd(&g_ttotal, 0ull);
        double rem = 1.0 - read_scalar(forget_p);
        long long num_rem = (long long)(rem * (double)NN);
        double denom = (double)BB * (double)num_rem;
        out[0] = (float)(sl / denom);
        out[1] = (float)((double)ts / (double)tt);
        // restore zero-invariant for next launch / graph replay
        g_rows_done = 0;
        g_sum_l3    = 0.0;
        g_sum_tsel  = 0ull;
        g_ttotal    = 0ull;
    }
}

// ---------------- host entry ----------------
extern "C" void kernel_launch(void* const* d_in, const int* in_sizes, int n_in,
                              void* d_out, int out_size) {
    const float* in1    = (const float*)d_in[0];
    const float* in2    = (const float*)d_in[1];
    const float* in3    = (const float*)d_in[2];
    const int*   tgt    = (const int*)d_in[3];
    const void*  forget = d_in[4];
    const void*  kdw    = d_in[5];
    float* out = (float*)d_out;

    k_compute<<<dim3(BLKX, BB), THREADS>>>(in1, in2, in3, tgt, kdw, forget);
    k_hist<<<dim3(SBLKX, BB), THREADS>>>();
    k_sum<<<dim3(SBLKX, BB), THREADS>>>(forget, out);

    (void)in_sizes; (void)n_in; (void)out_size;
}